// round 2
// baseline (speedup 1.0000x reference)
#include <cuda_runtime.h>
#include <cuda_bf16.h>

// ---------------------------------------------------------------------------
// Fused 23-op resize chain. One CTA per (n,c) image; whole chain in SMEM.
//
// Chain (H,W): 64x64 ->16x16->32x32->20x20->80x80->16x24->32x72 (nearest)
//   -> same cycle bilinear -> same cycle bicubic
//   -> nearest 54x144 -> bilinear 108x172 -> bilinear(align) 54x68
//   -> bicubic 43x61 -> bicubic(align) 47x30
// Max intermediate = 108*172 = 18576 floats.
// ---------------------------------------------------------------------------

#define NTH 512
#define BUF_ELEMS 18576
#define MAX_OUT 176
#define N_OPS 23

// SMEM: bufA | bufB | tbl_i[4*MAX_OUT] | tbl_w[4*MAX_OUT]
#define SMEM_BYTES ((2 * BUF_ELEMS + 8 * MAX_OUT) * 4)

struct OpDesc { int mode; int align; int oh; int ow; };  // mode: 0=nearest,1=bilinear,2=bicubic

__constant__ OpDesc OPS[N_OPS] = {
    {0, 0, 16, 16},  {0, 0, 32, 32},  {0, 0, 20, 20},  {0, 0, 80, 80},
    {0, 0, 16, 24},  {0, 0, 32, 72},
    {1, 0, 16, 16},  {1, 0, 32, 32},  {1, 0, 20, 20},  {1, 0, 80, 80},
    {1, 1, 16, 24},  {1, 1, 32, 72},
    {2, 0, 16, 16},  {2, 0, 32, 32},  {2, 0, 20, 20},  {2, 0, 80, 80},
    {2, 1, 16, 24},  {2, 1, 32, 72},
    {0, 0, 54, 144},   // nearest scale (1.7, 2)
    {1, 0, 108, 172},  // bilinear scale (2, 1.2)
    {1, 1, 54, 68},    // bilinear scale (0.5, 0.4) align
    {2, 0, 43, 61},    // bicubic scale (0.8, 0.9)
    {2, 1, 47, 30},    // bicubic scale (1.1, 0.5) align
};

// PyTorch bicubic kernel, A = -0.75  (exact reference formula order)
__device__ __forceinline__ float cc1(float t) {
    // ((A+2)*t - (A+3))*t*t + 1
    return (1.25f * t - 2.25f) * t * t + 1.0f;
}
__device__ __forceinline__ float cc2(float t) {
    // ((A*t - 5A)*t + 8A)*t - 4A
    return ((-0.75f * t + 3.75f) * t - 6.0f) * t + 3.0f;
}

// One separable 1D resize pass over SMEM.
//   vertical=1: resize H (in_len -> out_len) at width ncross; src/dst row-major width ncross
//   vertical=0: resize W (in_len -> out_len) over ncross rows; src width in_len, dst width out_len
__device__ __forceinline__ void do_pass(
    const float* __restrict__ src, float* __restrict__ dst,
    int in_len, int out_len, int ncross, int mode, int align, int vertical,
    int* __restrict__ tbl_i, float* __restrict__ tbl_w)
{
    const int tid = threadIdx.x;

    // ---- build per-output-position index/weight table (indices pre-multiplied
    //      by the along-axis stride so the inner loop is add-only) ----
    if (tid < out_len) {
        const int j = tid;
        const int sa = vertical ? ncross : 1;
        const int lim = in_len - 1;
        if (mode == 0) {
            // nearest: idx = min(floor(j * in/out), in-1)   (float32 math)
            float r = __fdiv_rn((float)in_len, (float)out_len);
            int i = (int)floorf((float)j * r);
            if (i > lim) i = lim;
            tbl_i[j] = i * sa;
        } else {
            float s;
            if (align) {
                float r = (out_len > 1)
                              ? __fdiv_rn((float)(in_len - 1), (float)(out_len - 1))
                              : 0.0f;
                s = (float)j * r;
            } else {
                float r = __fdiv_rn((float)in_len, (float)out_len);
                s = ((float)j + 0.5f) * r - 0.5f;
                if (mode == 1 && s < 0.0f) s = 0.0f;  // PyTorch clamps for linear only
            }
            float s0 = floorf(s);
            int i0 = (int)s0;
            float t = s - s0;
            if (mode == 1) {
                int i1 = i0 + 1;
                if (i1 > lim) i1 = lim;
                tbl_i[j]            = i0 * sa;
                tbl_i[MAX_OUT + j]  = i1 * sa;
                tbl_w[j] = t;
            } else {
                float w0 = cc2(t + 1.0f);
                float w1 = cc1(t);
                float w2 = cc1(1.0f - t);
                float w3 = cc2(2.0f - t);
#pragma unroll
                for (int k = 0; k < 4; k++) {
                    int i = i0 - 1 + k;
                    i = (i < 0) ? 0 : ((i > lim) ? lim : i);
                    tbl_i[k * MAX_OUT + j] = i * sa;
                }
                tbl_w[0 * MAX_OUT + j] = w0;
                tbl_w[1 * MAX_OUT + j] = w1;
                tbl_w[2 * MAX_OUT + j] = w2;
                tbl_w[3 * MAX_OUT + j] = w3;
            }
        }
    }
    __syncthreads();  // table ready AND previous pass's dst (our src) ready

    const int total = out_len * ncross;
    const int wf = vertical ? ncross : out_len;       // fast (contiguous) output dim
    const unsigned magic = 0xFFFFFFFFu / (unsigned)wf + 1u;  // exact for e < 2^16

    if (mode == 0) {
        for (int e = tid; e < total; e += NTH) {
            unsigned q = __umulhi((unsigned)e, magic);
            int r = e - (int)q * wf;
            int along = vertical ? (int)q : r;
            int base  = vertical ? r : (int)q * in_len;
            dst[e] = src[base + tbl_i[along]];
        }
    } else if (mode == 1) {
        for (int e = tid; e < total; e += NTH) {
            unsigned q = __umulhi((unsigned)e, magic);
            int r = e - (int)q * wf;
            int along = vertical ? (int)q : r;
            int base  = vertical ? r : (int)q * in_len;
            float a = src[base + tbl_i[along]];
            float b = src[base + tbl_i[MAX_OUT + along]];
            float t = tbl_w[along];
            dst[e] = a + (b - a) * t;   // reference: a + (b-a)*t
        }
    } else {
        for (int e = tid; e < total; e += NTH) {
            unsigned q = __umulhi((unsigned)e, magic);
            int r = e - (int)q * wf;
            int along = vertical ? (int)q : r;
            int base  = vertical ? r : (int)q * in_len;
            float v;
            v  = src[base + tbl_i[0 * MAX_OUT + along]] * tbl_w[0 * MAX_OUT + along];
            v += src[base + tbl_i[1 * MAX_OUT + along]] * tbl_w[1 * MAX_OUT + along];
            v += src[base + tbl_i[2 * MAX_OUT + along]] * tbl_w[2 * MAX_OUT + along];
            v += src[base + tbl_i[3 * MAX_OUT + along]] * tbl_w[3 * MAX_OUT + along];
            dst[e] = v;
        }
    }
    __syncthreads();  // dst complete before next pass rewrites tables / reads dst
}

__global__ void __launch_bounds__(NTH, 1)
resize_chain_kernel(const float* __restrict__ in, float* __restrict__ out)
{
    extern __shared__ float smem[];
    float* bufA  = smem;
    float* bufB  = smem + BUF_ELEMS;
    int*   tbl_i = (int*)(smem + 2 * BUF_ELEMS);
    float* tbl_w = (float*)(tbl_i + 4 * MAX_OUT);

    const int tid = threadIdx.x;
    const float* __restrict__ g = in + (size_t)blockIdx.x * 4096;  // 64*64

    for (int i = tid; i < 4096; i += NTH) bufA[i] = __ldg(&g[i]);
    // visibility of bufA is covered by the __syncthreads after the first
    // pass's table build (table build touches no image data).

    int h = 64, w = 64;
    float* cur = bufA;
    float* oth = bufB;

#pragma unroll 1
    for (int op = 0; op < N_OPS; op++) {
        OpDesc d = OPS[op];
        // vertical: H resize at width w
        do_pass(cur, oth, h, d.oh, w, d.mode, d.align, 1, tbl_i, tbl_w);
        h = d.oh;
        { float* t = cur; cur = oth; oth = t; }
        // horizontal: W resize over h rows
        do_pass(cur, oth, w, d.ow, h, d.mode, d.align, 0, tbl_i, tbl_w);
        w = d.ow;
        { float* t = cur; cur = oth; oth = t; }
    }

    // final: 47 x 30 = 1410 floats, contiguous per image
    float* __restrict__ o = out + (size_t)blockIdx.x * 1410;
    for (int i = tid; i < 1410; i += NTH) o[i] = cur[i];
}

extern "C" void kernel_launch(void* const* d_in, const int* in_sizes, int n_in,
                              void* d_out, int out_size)
{
    const float* x = (const float*)d_in[0];
    float* out = (float*)d_out;
    int nimg = in_sizes[0] / 4096;  // (32*256) images of 64*64

    cudaFuncSetAttribute(resize_chain_kernel,
                         cudaFuncAttributeMaxDynamicSharedMemorySize, SMEM_BYTES);
    resize_chain_kernel<<<nimg, NTH, SMEM_BYTES>>>(x, out);
}

// round 5
// speedup vs baseline: 28.5899x; 28.5899x over previous
#include <cuda_runtime.h>
#include <cuda_bf16.h>

// ---------------------------------------------------------------------------
// The 23-op resize chain is a tensor product of two 1D linear operators:
//   out = M_H (47x64) . X (64x64) . M_W^T (64x30)
// First op (nearest 64->16, ratio exactly 4.0) reads only rows/cols {0,4,..,60},
// so both matrices have exactly 16 nonzero columns:
//   out = MH (47x16) . X' (16x16 gathered stride-4) . MW^T (16x30)
// Kernel 1 composes MH/MW on device (exact same fp32 index/weight math as the
// reference); kernel 2 applies the two tiny GEMMs, one warp per image, storing
// results straight from registers (row-contiguous across lanes).
// ---------------------------------------------------------------------------

#define NTH 256
#define IMGS_PER_CTA 8
#define MAX_LEN 172          // max intermediate length across BOTH axes (W hits 172)

// per-axis size chains: initial 64 + 23 outputs
__constant__ int H_SIZES[24] = {64, 16,32,20,80,16,32, 16,32,20,80,16,32,
                                16,32,20,80,16,32, 54,108,54,43,47};
__constant__ int W_SIZES[24] = {64, 16,32,20,80,24,72, 16,32,20,80,24,72,
                                16,32,20,80,24,72, 144,172,68,61,30};
__constant__ int MODE_C[23]  = {0,0,0,0,0,0, 1,1,1,1,1,1, 2,2,2,2,2,2, 0,1,1,2,2};
__constant__ int ALIGN_C[23] = {0,0,0,0,0,0, 0,0,0,0,1,1, 0,0,0,0,1,1, 0,0,1,0,1};

// composed operators (compressed to the 16 live columns) + compose scratch
__device__ float MH_g[47 * 16];
__device__ float MW_g[30 * 16];
__device__ float g_scr[2][2][MAX_LEN * 64];   // [axis][pingpong][rows x 64]

// PyTorch bicubic kernel, A = -0.75 (exact reference formula order)
__device__ __forceinline__ float cc1(float t) {
    return (1.25f * t - 2.25f) * t * t + 1.0f;
}
__device__ __forceinline__ float cc2(float t) {
    return ((-0.75f * t + 3.75f) * t - 6.0f) * t + 3.0f;
}

// ---------------------------------------------------------------------------
// Kernel 1: compose the 23-stage 1D operator chain for one axis per block.
// ---------------------------------------------------------------------------
__global__ void compose_kernel()
{
    const int axis = blockIdx.x;           // 0 = H, 1 = W
    const int tid  = threadIdx.x;
    float* bufA = g_scr[axis][0];
    float* bufB = g_scr[axis][1];

    // start: identity 64x64
    for (int i = tid; i < 64 * 64; i += blockDim.x)
        bufA[i] = ((i >> 6) == (i & 63)) ? 1.0f : 0.0f;
    __syncthreads();

    float* cur = bufA;
    float* nxt = bufB;

    for (int op = 0; op < 23; op++) {
        const int inl  = axis ? W_SIZES[op]     : H_SIZES[op];
        const int outl = axis ? W_SIZES[op + 1] : H_SIZES[op + 1];
        const int mode  = MODE_C[op];
        const int align = ALIGN_C[op];
        const int lim = inl - 1;

        for (int e = tid; e < outl * 64; e += blockDim.x) {
            const int j = e >> 6;
            const int c = e & 63;
            float v;
            if (mode == 0) {
                // nearest: idx = min(floor(j * in/out), in-1), fp32
                float r = __fdiv_rn((float)inl, (float)outl);
                int i = (int)floorf((float)j * r);
                if (i > lim) i = lim;
                v = cur[i * 64 + c];
            } else {
                float s;
                if (align) {
                    float r = (outl > 1)
                                  ? __fdiv_rn((float)(inl - 1), (float)(outl - 1))
                                  : 0.0f;
                    s = (float)j * r;
                } else {
                    float r = __fdiv_rn((float)inl, (float)outl);
                    s = ((float)j + 0.5f) * r - 0.5f;
                    if (mode == 1 && s < 0.0f) s = 0.0f;  // clamp for linear only
                }
                float s0 = floorf(s);
                int   i0 = (int)s0;
                float t  = s - s0;
                if (mode == 1) {
                    int i1 = i0 + 1; if (i1 > lim) i1 = lim;
                    float a = cur[i0 * 64 + c];
                    float b = cur[i1 * 64 + c];
                    v = a + (b - a) * t;        // reference form
                } else {
                    float w0 = cc2(t + 1.0f);
                    float w1 = cc1(t);
                    float w2 = cc1(1.0f - t);
                    float w3 = cc2(2.0f - t);
                    int k0 = i0 - 1, k1 = i0, k2 = i0 + 1, k3 = i0 + 2;
                    k0 = (k0 < 0) ? 0 : ((k0 > lim) ? lim : k0);
                    k1 = (k1 < 0) ? 0 : ((k1 > lim) ? lim : k1);
                    k2 = (k2 < 0) ? 0 : ((k2 > lim) ? lim : k2);
                    k3 = (k3 < 0) ? 0 : ((k3 > lim) ? lim : k3);
                    // same summation order as reference (k = 0..3)
                    v = cur[k0 * 64 + c] * w0 + cur[k1 * 64 + c] * w1
                      + cur[k2 * 64 + c] * w2 + cur[k3 * 64 + c] * w3;
                }
            }
            nxt[e] = v;
        }
        __syncthreads();
        float* tmp = cur; cur = nxt; nxt = tmp;
    }

    // compress: keep only columns {0,4,...,60}
    if (axis == 0) {
        for (int e = tid; e < 47 * 16; e += blockDim.x)
            MH_g[e] = cur[(e >> 4) * 64 + (e & 15) * 4];
    } else {
        for (int e = tid; e < 30 * 16; e += blockDim.x)
            MW_g[e] = cur[(e >> 4) * 64 + (e & 15) * 4];
    }
}

// ---------------------------------------------------------------------------
// Kernel 2: one warp per image.  out(47x30) = MH(47x16) . X'(16x16) . MW^T(16x30)
// Stage 1 (W first, fewer MACs): T[a] = sum_b X'[a][b] * MW[lane][b]
// Stage 2: out[i][lane] = sum_a MH[i][a] * T[a], stored straight to gmem
// (lanes 0..29 of one row write 120 contiguous bytes). Lanes 30,31 idle.
// ---------------------------------------------------------------------------
__global__ void __launch_bounds__(NTH)
apply_kernel(const float* __restrict__ in, float* __restrict__ out, int nimg)
{
    __shared__ float sMH[47 * 16];
    __shared__ float sX[IMGS_PER_CTA][16 * 16];

    const int tid  = threadIdx.x;
    const int warp = tid >> 5;
    const int lane = tid & 31;
    const int img  = blockIdx.x * IMGS_PER_CTA + warp;
    const bool valid = (img < nimg);

    for (int i = tid; i < 47 * 16; i += NTH) sMH[i] = MH_g[i];

    // per-lane MW row (lane j -> MW[j][0..15]); lanes >=30 read row 0 (unused)
    float mw[16];
    {
        const int j = (lane < 30) ? lane : 0;
#pragma unroll
        for (int b = 0; b < 16; b++) mw[b] = MW_g[j * 16 + b];
    }

    // gather X' = X[4a][4b] (16x16) into SMEM
    if (valid) {
        const float* __restrict__ src = in + (size_t)img * 4096;
#pragma unroll
        for (int i = 0; i < 8; i++) {
            int e = lane * 8 + i;
            int a = e >> 4, b = e & 15;
            sX[warp][e] = __ldg(&src[a * 256 + b * 4]);  // row 4a (stride 64), col 4b
        }
    }
    __syncthreads();   // sMH + sX ready

    // stage 1: T[a] for this lane's column
    float T[16];
#pragma unroll
    for (int a = 0; a < 16; a++) {
        float acc = 0.0f;
#pragma unroll
        for (int b = 0; b < 16; b++)
            acc = fmaf(sX[warp][a * 16 + b], mw[b], acc);
        T[a] = acc;
    }

    // stage 2: compute + store each output row directly from registers
    if (valid && lane < 30) {
        float* __restrict__ dst = out + (size_t)img * 1410 + lane;
#pragma unroll 4
        for (int i = 0; i < 47; i++) {
            float acc = 0.0f;
#pragma unroll
            for (int a = 0; a < 16; a++)
                acc = fmaf(sMH[i * 16 + a], T[a], acc);
            dst[i * 30] = acc;
        }
    }
}

extern "C" void kernel_launch(void* const* d_in, const int* in_sizes, int n_in,
                              void* d_out, int out_size)
{
    const float* x = (const float*)d_in[0];
    float* out = (float*)d_out;
    const int nimg = in_sizes[0] / 4096;   // 8192 images of 64x64

    compose_kernel<<<2, 256>>>();
    apply_kernel<<<(nimg + IMGS_PER_CTA - 1) / IMGS_PER_CTA, NTH>>>(x, out, nimg);
}

// round 6
// speedup vs baseline: 72.0503x; 2.5201x over previous
#include <cuda_runtime.h>
#include <cstring>
#include <cmath>

// ---------------------------------------------------------------------------
// The 23-op resize chain == out = MH (47x16) . X'(16x16, stride-4 gather) . MW^T (16x30)
// (first op is nearest 64->16 ratio exactly 4.0 => only rows/cols {0,4,..,60} live).
// MH/MW are composed on the HOST in fp32 (same index/weight math as reference;
// volatile blocks FMA contraction in the index-critical path) and shipped via
// cudaMemcpyToSymbolAsync (graph-capturable).
// Kernel: 1 warp = 4 images, image pairs packed into f32x2 lanes; fma.rn.f32x2
// halves FFMA issue; MH duplicated into (w,w) 64-bit words so one broadcast
// LDS.64 feeds both packed accumulators.
// ---------------------------------------------------------------------------

#define NTH   256
#define WARPS 8
#define IPW   4                       // images per warp
#define IMGS_PER_CTA (WARPS * IPW)    // 32

__device__ unsigned long long gMH2[47 * 16];  // (w,w) duplicated fp32 pairs
__device__ float              gMW[30 * 16];

// ---------------------------------------------------------------------------
// Host-side operator composition (fp32, mirrors reference semantics)
// ---------------------------------------------------------------------------
static const int hH_SIZES[24] = {64, 16,32,20,80,16,32, 16,32,20,80,16,32,
                                 16,32,20,80,16,32, 54,108,54,43,47};
static const int hW_SIZES[24] = {64, 16,32,20,80,24,72, 16,32,20,80,24,72,
                                 16,32,20,80,24,72, 144,172,68,61,30};
static const int hMODE[23]  = {0,0,0,0,0,0, 1,1,1,1,1,1, 2,2,2,2,2,2, 0,1,1,2,2};
static const int hALIGN[23] = {0,0,0,0,0,0, 0,0,0,0,1,1, 0,0,0,0,1,1, 0,0,1,0,1};

static inline float h_cc1(float t) {            // A=-0.75: ((A+2)t-(A+3))t^2+1
    return (1.25f * t - 2.25f) * t * t + 1.0f;
}
static inline float h_cc2(float t) {            // ((At-5A)t+8A)t-4A
    return ((-0.75f * t + 3.75f) * t - 6.0f) * t + 3.0f;
}

// compose the 23-stage chain for one axis; result in `cur` (rows x 64)
static void h_compose(const int* sizes, float* cur, float* nxt)
{
    for (int r = 0; r < 64; r++)
        for (int c = 0; c < 64; c++)
            cur[r * 64 + c] = (r == c) ? 1.0f : 0.0f;

    for (int op = 0; op < 23; op++) {
        const int inl  = sizes[op];
        const int outl = sizes[op + 1];
        const int mode  = hMODE[op];
        const int align = hALIGN[op];
        const int lim = inl - 1;
        const float r_no  = (float)inl / (float)outl;
        const float r_al  = (outl > 1) ? (float)(inl - 1) / (float)(outl - 1) : 0.0f;

        for (int j = 0; j < outl; j++) {
            if (mode == 0) {
                volatile float p = (float)j * r_no;   // single mul, exact IEEE
                int i = (int)floorf(p);
                if (i > lim) i = lim;
                for (int c = 0; c < 64; c++) nxt[j * 64 + c] = cur[i * 64 + c];
            } else {
                float s;
                if (align) {
                    volatile float p = (float)j * r_al;
                    s = p;
                } else {
                    volatile float p = ((float)j + 0.5f) * r_no;  // block contraction
                    s = p - 0.5f;
                    if (mode == 1 && s < 0.0f) s = 0.0f;
                }
                float s0 = floorf(s);
                int   i0 = (int)s0;
                float t  = s - s0;
                if (mode == 1) {
                    int i1 = i0 + 1; if (i1 > lim) i1 = lim;
                    for (int c = 0; c < 64; c++) {
                        float a = cur[i0 * 64 + c];
                        float b = cur[i1 * 64 + c];
                        nxt[j * 64 + c] = a + (b - a) * t;
                    }
                } else {
                    float w0 = h_cc2(t + 1.0f), w1 = h_cc1(t);
                    float w2 = h_cc1(1.0f - t), w3 = h_cc2(2.0f - t);
                    int k0 = i0 - 1, k1 = i0, k2 = i0 + 1, k3 = i0 + 2;
                    k0 = (k0 < 0) ? 0 : ((k0 > lim) ? lim : k0);
                    k1 = (k1 < 0) ? 0 : ((k1 > lim) ? lim : k1);
                    k2 = (k2 < 0) ? 0 : ((k2 > lim) ? lim : k2);
                    k3 = (k3 < 0) ? 0 : ((k3 > lim) ? lim : k3);
                    for (int c = 0; c < 64; c++)
                        nxt[j * 64 + c] = cur[k0 * 64 + c] * w0 + cur[k1 * 64 + c] * w1
                                        + cur[k2 * 64 + c] * w2 + cur[k3 * 64 + c] * w3;
                }
            }
        }
        // swap
        for (int e = 0; e < outl * 64; e++) cur[e] = nxt[e];
    }
}

// ---------------------------------------------------------------------------
// Device helpers: packed f32x2 ops
// ---------------------------------------------------------------------------
__device__ __forceinline__ unsigned long long fma2(
    unsigned long long a, unsigned long long b, unsigned long long c)
{
    unsigned long long d;
    asm("fma.rn.f32x2 %0, %1, %2, %3;" : "=l"(d) : "l"(a), "l"(b), "l"(c));
    return d;
}
__device__ __forceinline__ unsigned long long pack2(float lo, float hi)
{
    unsigned long long d;
    asm("mov.b64 %0, {%1, %2};" : "=l"(d) : "f"(lo), "f"(hi));
    return d;
}
__device__ __forceinline__ void unpack2(unsigned long long v, float& lo, float& hi)
{
    asm("mov.b64 {%0, %1}, %2;" : "=f"(lo), "=f"(hi) : "l"(v));
}

// ---------------------------------------------------------------------------
// Apply kernel: warp handles 4 images (2 packed pairs).
// Stage 1: T2[p][a] = sum_b Xpair[p][a][b] * (mw,mw)   (LDS.64 broadcast of X)
// Stage 2: out[i][lane](x4 imgs) = sum_a (MH,MH)[i][a] * T2[p][a]
// ---------------------------------------------------------------------------
__global__ void __launch_bounds__(NTH, 2)
apply_kernel(const float* __restrict__ in, float* __restrict__ out, int nimg)
{
    __shared__ unsigned long long sMH2[47 * 16];
    __shared__ unsigned long long sX[WARPS][2][16 * 16];  // interleaved image pairs

    const int tid  = threadIdx.x;
    const int warp = tid >> 5;
    const int lane = tid & 31;

    for (int i = tid; i < 47 * 16; i += NTH) sMH2[i] = gMH2[i];

    const int img0 = (blockIdx.x * WARPS + warp) * IPW;

    // per-lane MW row, packed (w,w); lanes >=30 use row 0 (results unstored)
    unsigned long long mw2[16];
    {
        const int j = (lane < 30) ? lane : 0;
        const float4* mwp = (const float4*)(gMW + j * 16);
#pragma unroll
        for (int q = 0; q < 4; q++) {
            float4 v = mwp[q];
            mw2[q * 4 + 0] = pack2(v.x, v.x);
            mw2[q * 4 + 1] = pack2(v.y, v.y);
            mw2[q * 4 + 2] = pack2(v.z, v.z);
            mw2[q * 4 + 3] = pack2(v.w, v.w);
        }
    }

    // gather X' (16x16, stride-4 both dims) for 4 images, interleaved by pair
#pragma unroll
    for (int k = 0; k < IPW; k++) {
        if (img0 + k < nimg) {
            const float* __restrict__ src = in + (size_t)(img0 + k) * 4096;
            float* sdst = (float*)sX[warp][k >> 1];
#pragma unroll
            for (int i2 = 0; i2 < 8; i2++) {
                int a = i2 * 2 + (lane >> 4);
                int b = lane & 15;
                sdst[(a * 16 + b) * 2 + (k & 1)] = __ldg(&src[a * 256 + b * 4]);
            }
        }
    }
    __syncthreads();  // sMH2 + sX ready

    // stage 1
    unsigned long long T2[2][16];
#pragma unroll
    for (int p = 0; p < 2; p++) {
#pragma unroll
        for (int a = 0; a < 16; a++) {
            unsigned long long acc = 0ULL;  // (+0.0f, +0.0f)
#pragma unroll
            for (int b = 0; b < 16; b++)
                acc = fma2(sX[warp][p][a * 16 + b], mw2[b], acc);
            T2[p][a] = acc;
        }
    }

    // stage 2 + direct stores (lanes 0..29 write a contiguous 120B row chunk)
    const bool ln = (lane < 30);
    const bool v0 = ln && (img0 + 0 < nimg);
    const bool v1 = ln && (img0 + 1 < nimg);
    const bool v2 = ln && (img0 + 2 < nimg);
    const bool v3 = ln && (img0 + 3 < nimg);
    float* __restrict__ d0 = out + (size_t)(img0 + 0) * 1410 + lane;
    float* __restrict__ d1 = out + (size_t)(img0 + 1) * 1410 + lane;
    float* __restrict__ d2 = out + (size_t)(img0 + 2) * 1410 + lane;
    float* __restrict__ d3 = out + (size_t)(img0 + 3) * 1410 + lane;

#pragma unroll 1
    for (int i = 0; i < 47; i++) {
        unsigned long long acc0 = 0ULL, acc1 = 0ULL;
#pragma unroll
        for (int a = 0; a < 16; a++) {
            unsigned long long m = sMH2[i * 16 + a];   // broadcast LDS.64
            acc0 = fma2(m, T2[0][a], acc0);
            acc1 = fma2(m, T2[1][a], acc1);
        }
        float o0, o1, o2, o3;
        unpack2(acc0, o0, o1);
        unpack2(acc1, o2, o3);
        if (v0) d0[i * 30] = o0;
        if (v1) d1[i * 30] = o1;
        if (v2) d2[i * 30] = o2;
        if (v3) d3[i * 30] = o3;
    }
}

// ---------------------------------------------------------------------------
extern "C" void kernel_launch(void* const* d_in, const int* in_sizes, int n_in,
                              void* d_out, int out_size)
{
    const float* x = (const float*)d_in[0];
    float* out = (float*)d_out;
    const int nimg = in_sizes[0] / 4096;   // 8192 images of 64x64

    // host-side compose (runs at capture time; buffers static so the graph's
    // H2D memcpy nodes keep reading valid, deterministic data on every replay)
    static unsigned long long hMH2[47 * 16];
    static float hMW[30 * 16];
    static float bufA[172 * 64], bufB[172 * 64];

    h_compose(hH_SIZES, bufA, bufB);           // H axis -> 47 x 64
    for (int i = 0; i < 47; i++)
        for (int a = 0; a < 16; a++) {
            float f = bufA[i * 64 + a * 4];    // compress: live cols {0,4,..,60}
            unsigned int bits;
            memcpy(&bits, &f, 4);
            hMH2[i * 16 + a] = (unsigned long long)bits | ((unsigned long long)bits << 32);
        }

    h_compose(hW_SIZES, bufA, bufB);           // W axis -> 30 x 64
    for (int j = 0; j < 30; j++)
        for (int b = 0; b < 16; b++)
            hMW[j * 16 + b] = bufA[j * 64 + b * 4];

    cudaMemcpyToSymbolAsync(gMH2, hMH2, sizeof(hMH2), 0, cudaMemcpyHostToDevice, 0);
    cudaMemcpyToSymbolAsync(gMW,  hMW,  sizeof(hMW),  0, cudaMemcpyHostToDevice, 0);

    apply_kernel<<<(nimg + IMGS_PER_CTA - 1) / IMGS_PER_CTA, NTH>>>(x, out, nimg);
}